// round 8
// baseline (speedup 1.0000x reference)
#include <cuda_runtime.h>
#include <cuda_bf16.h>
#include <cstdint>
#include <math.h>

#define BSZ 8192
#define NK  2048
#define BM  128
#define BN  128
#define BKF 32                    // fp32 K consumed per mainloop iteration
#define TILE_B 8192               // 128 rows x 32 bf16 = 8KB
#define STAGE_B (4*TILE_B)        // Ahi, Alo, Bhi, Blo = 32KB
#define NSTAGE 5
#define SMEM_BYTES (NSTAGE*STAGE_B)   // 160KB -> 1 CTA/SM, deep pipeline
#define NTHR 512                  // 16 warps, 4x4 grid of 32x32 warp tiles

// ---------------- scratch (static device globals; no runtime alloc) ----------------
__device__ __nv_bfloat16 g_xhi[(size_t)BSZ*NK], g_xlo[(size_t)BSZ*NK];
__device__ __nv_bfloat16 g_hhi[(size_t)BSZ*NK], g_hlo[(size_t)BSZ*NK];
__device__ __nv_bfloat16 g_whi[(size_t)6*NK*NK], g_wlo[(size_t)6*NK*NK]; // [w][N][K]
__device__ __nv_bfloat16 g_rhhi[(size_t)BSZ*NK], g_rhlo[(size_t)BSZ*NK];
__device__ float g_Z [(size_t)BSZ*NK];
__device__ float g_WH[(size_t)BSZ*NK];

// ---------------- helpers ----------------
__device__ __forceinline__ uint32_t smem_u32(const void* p) {
    uint32_t a;
    asm("{ .reg .u64 t; cvta.to.shared.u64 t, %1; cvt.u32.u64 %0, t; }" : "=r"(a) : "l"(p));
    return a;
}
__device__ __forceinline__ void cp16(uint32_t dst, const char* src) {
    asm volatile("cp.async.cg.shared.global [%0], [%1], 16;"
                 :: "r"(dst), "l"(src) : "memory");
}
#define CP_COMMIT() asm volatile("cp.async.commit_group;" ::: "memory")
#define CP_WAIT(n)  asm volatile("cp.async.wait_group %0;" :: "n"(n) : "memory")

__device__ __forceinline__ void ldm4(uint32_t* r, uint32_t addr) {
    asm volatile("ldmatrix.sync.aligned.m8n8.x4.shared.b16 {%0,%1,%2,%3}, [%4];"
                 : "=r"(r[0]), "=r"(r[1]), "=r"(r[2]), "=r"(r[3]) : "r"(addr));
}
__device__ __forceinline__ void mma16816(float* d, const uint32_t* a,
                                         uint32_t b0, uint32_t b1) {
    asm volatile(
        "mma.sync.aligned.m16n8k16.row.col.f32.bf16.bf16.f32 "
        "{%0,%1,%2,%3}, {%4,%5,%6,%7}, {%8,%9}, {%0,%1,%2,%3};"
        : "+f"(d[0]), "+f"(d[1]), "+f"(d[2]), "+f"(d[3])
        : "r"(a[0]), "r"(a[1]), "r"(a[2]), "r"(a[3]), "r"(b0), "r"(b1));
}
__device__ __forceinline__ float sigf(float x) { return 1.0f / (1.0f + __expf(-x)); }

__device__ __forceinline__ void split2(float f0, float f1, uint32_t& hi, uint32_t& lo) {
    __nv_bfloat16 h0 = __float2bfloat16_rn(f0);
    __nv_bfloat16 h1 = __float2bfloat16_rn(f1);
    __nv_bfloat16 l0 = __float2bfloat16_rn(f0 - __bfloat162float(h0));
    __nv_bfloat16 l1 = __float2bfloat16_rn(f1 - __bfloat162float(h1));
    hi = (uint32_t)__bfloat16_as_ushort(h0) | ((uint32_t)__bfloat16_as_ushort(h1) << 16);
    lo = (uint32_t)__bfloat16_as_ushort(l0) | ((uint32_t)__bfloat16_as_ushort(l1) << 16);
}

// Swizzled address inside a 128x32-bf16 tile (two logical 64B rows packed per
// 128B line).  row: 0..127, c2: 16B-chunk index within row (0..3).
__device__ __forceinline__ uint32_t swofs(uint32_t row, uint32_t c2) {
    uint32_t p = row >> 1, h = row & 1;
    return p * 128 + (((((h << 2) | c2) ^ (p & 7)) << 4));
}

// ---------------- prep: elementwise split of x / h ----------------
__global__ void cvt_split(const float4* __restrict__ in, int which) {
    size_t i = (size_t)blockIdx.x * 256 + threadIdx.x;   // BSZ*NK/4 threads
    uint2* hi = (uint2*)(which ? g_hhi : g_xhi);
    uint2* lo = (uint2*)(which ? g_hlo : g_xlo);
    float4 v = in[i];
    uint32_t h01, l01, h23, l23;
    split2(v.x, v.y, h01, l01);
    split2(v.z, v.w, h23, l23);
    hi[i] = make_uint2(h01, h23);
    lo[i] = make_uint2(l01, l23);
}

// ---------------- prep: transpose + split of all 6 weights ----------------
__global__ void wt_split(const float* __restrict__ W0, const float* __restrict__ W1,
                         const float* __restrict__ W2, const float* __restrict__ W3,
                         const float* __restrict__ W4, const float* __restrict__ W5) {
    __shared__ float t[32][33];
    int w = blockIdx.z;
    const float* src = (w == 0) ? W0 : (w == 1) ? W1 : (w == 2) ? W2
                     : (w == 3) ? W3 : (w == 4) ? W4 : W5;
    int nt = blockIdx.x * 32, kt = blockIdx.y * 32;
    int tx = threadIdx.x & 31, ty = threadIdx.x >> 5;
    #pragma unroll
    for (int j = 0; j < 4; j++) {
        int r = ty + j * 8;
        t[r][tx] = src[(size_t)(kt + r) * NK + nt + tx];
    }
    __syncthreads();
    size_t wbase = (size_t)w * NK * NK;
    #pragma unroll
    for (int j = 0; j < 4; j++) {
        int r = ty + j * 8;
        float v = t[tx][r];
        __nv_bfloat16 hv = __float2bfloat16_rn(v);
        __nv_bfloat16 lv = __float2bfloat16_rn(v - __bfloat162float(hv));
        size_t o = wbase + (size_t)(nt + r) * NK + kt + tx;
        g_whi[o] = hv;
        g_wlo[o] = lv;
    }
}

// ---------------- mma.sync mainloop (shared by both stages) ----------------
// acc += A[m0:m0+128, :] @ B[ncol:ncol+128, :]^T over `iters` chunks of 32
// fp32-K each; switches to operand set 2 at iter 64 (two-pass when iters=128).
// 16 warps, 4x4 grid of 32x32 warp tiles, 5-stage cp.async pipeline.
__device__ __forceinline__ void gemm_mainloop(
    const __nv_bfloat16* a1h, const __nv_bfloat16* a1l,
    const __nv_bfloat16* b1h, const __nv_bfloat16* b1l,
    const __nv_bfloat16* a2h, const __nv_bfloat16* a2l,
    const __nv_bfloat16* b2h, const __nv_bfloat16* b2l,
    int iters, int m0, int ncol, uint32_t smem,
    float (&acc)[2][4][4])
{
    const int tid  = threadIdx.x;
    const int lane = tid & 31;
    const int wid  = tid >> 5;
    const int wm   = wid >> 2;     // 0..3
    const int wn   = wid & 3;      // 0..3

    // --- cp.async write addressing: 1 chunk per 8KB tile per thread ---
    uint32_t row = (uint32_t)tid >> 2;    // 0..127
    uint32_t cch = (uint32_t)tid & 3;
    const uint32_t swr  = swofs(row, cch);
    const uint32_t offMB = ((uint32_t)(m0 + row) * NK + cch * 8) * 2;
    const uint32_t offNB = ((uint32_t)(ncol + row) * NK + cch * 8) * 2;

    auto loads = [&](int L, uint32_t sb) {
        bool p2 = (L >= 64);
        const char* ah = (const char*)(p2 ? a2h : a1h);
        const char* al = (const char*)(p2 ? a2l : a1l);
        const char* bh = (const char*)(p2 ? b2h : b1h);
        const char* bl = (const char*)(p2 ? b2l : b1l);
        uint32_t kk = ((uint32_t)L & 63u) * (BKF * 2);     // byte offset in K
        uint32_t om = offMB + kk, on = offNB + kk;
        cp16(sb +            swr, ah + om);
        cp16(sb + TILE_B   + swr, al + om);
        cp16(sb + 2*TILE_B + swr, bh + on);
        cp16(sb + 3*TILE_B + swr, bl + on);
        CP_COMMIT();
    };

    // --- ldmatrix read addressing (constants per thread) ---
    const uint32_t r_in = ((lane >> 3) & 1) * 8 + (lane & 7);
    const uint32_t c2b  = (lane >> 4);             // 0 or 1 (16B half of k16)
    uint32_t offA[2][2], offB[2][2];
    #pragma unroll
    for (int mf = 0; mf < 2; mf++)
        #pragma unroll
        for (int ks = 0; ks < 2; ks++)
            offA[mf][ks] = swofs(wm * 32 + mf * 16 + r_in, ks * 2 + c2b);
    #pragma unroll
    for (int nb = 0; nb < 2; nb++)
        #pragma unroll
        for (int ks = 0; ks < 2; ks++)
            offB[nb][ks] = swofs(wn * 32 + nb * 16 + r_in, ks * 2 + c2b);

    auto compute_ks = [&](uint32_t Ah, int ks) {
        uint32_t Al = Ah + TILE_B;
        uint32_t Bh = Ah + 2 * TILE_B;
        uint32_t Bl = Ah + 3 * TILE_B;
        uint32_t a[2][2][4];
        #pragma unroll
        for (int mf = 0; mf < 2; mf++) {
            ldm4(a[mf][0], Ah + offA[mf][ks]);
            ldm4(a[mf][1], Al + offA[mf][ks]);
        }
        #pragma unroll
        for (int nb = 0; nb < 2; nb++) {
            uint32_t bh4[4], bl4[4];
            ldm4(bh4, Bh + offB[nb][ks]);
            ldm4(bl4, Bl + offB[nb][ks]);
            // term-major emission: accumulator reuse distance = 4 MMAs
            #pragma unroll
            for (int mf = 0; mf < 2; mf++)
                #pragma unroll
                for (int hf = 0; hf < 2; hf++)
                    mma16816(acc[mf][nb * 2 + hf], a[mf][0], bh4[hf], bh4[2 + hf]); // hi*hi
            #pragma unroll
            for (int mf = 0; mf < 2; mf++)
                #pragma unroll
                for (int hf = 0; hf < 2; hf++)
                    mma16816(acc[mf][nb * 2 + hf], a[mf][0], bl4[hf], bl4[2 + hf]); // hi*lo
            #pragma unroll
            for (int mf = 0; mf < 2; mf++)
                #pragma unroll
                for (int hf = 0; hf < 2; hf++)
                    mma16816(acc[mf][nb * 2 + hf], a[mf][1], bh4[hf], bh4[2 + hf]); // lo*hi
        }
    };

    const uint32_t send = smem + (uint32_t)NSTAGE * STAGE_B;
    loads(0, smem);
    loads(1, smem + STAGE_B);
    loads(2, smem + 2u * STAGE_B);
    loads(3, smem + 3u * STAGE_B);
    uint32_t cs = smem;                 // stage being computed
    uint32_t ls = smem + 4u * STAGE_B;  // stage being loaded (i+4)
    for (int i = 0; i < iters; i++) {
        if (i + 3 < iters)      { CP_WAIT(3); }
        else if (i + 2 < iters) { CP_WAIT(2); }
        else if (i + 1 < iters) { CP_WAIT(1); }
        else                    { CP_WAIT(0); }
        __syncthreads();
        compute_ks(cs, 0);
        if (i + 4 < iters) loads(i + 4, ls);
        compute_ks(cs, 1);
        __syncthreads();
        cs += STAGE_B; if (cs == send) cs = smem;
        ls += STAGE_B; if (ls == send) ls = smem;
    }
}

// ---------------- stage 1 ----------------
// seg 0: g_Z  = sigmoid(x@Wz + h@Uz + bz)
// seg 1: g_rh = split( sigmoid(x@Wr + h@Ur + br) * h )
// seg 2: g_WH = x@Wh
__global__ __launch_bounds__(NTHR, 1) void gru_s1(
    const float* __restrict__ hprev, const float* __restrict__ bz,
    const float* __restrict__ br)
{
    extern __shared__ char smraw[];
    uint32_t smem = smem_u32(smraw);
    const int lane = threadIdx.x & 31;
    const int wid  = threadIdx.x >> 5;
    const int wm = wid >> 2, wn = wid & 3;
    const int g = lane >> 2, tig = lane & 3;

    int seg  = blockIdx.x >> 4;
    int ncol = (blockIdx.x & 15) * BN;
    int m0   = blockIdx.y * BM;
    size_t wsz = (size_t)NK * NK;
    const __nv_bfloat16* b1h = g_whi + (size_t)seg * wsz;
    const __nv_bfloat16* b1l = g_wlo + (size_t)seg * wsz;
    const __nv_bfloat16* b2h = g_whi + (size_t)(3 + seg) * wsz;
    const __nv_bfloat16* b2l = g_wlo + (size_t)(3 + seg) * wsz;
    int iters = (seg < 2) ? 128 : 64;

    float acc[2][4][4];
    #pragma unroll
    for (int i = 0; i < 2; i++)
        #pragma unroll
        for (int j = 0; j < 4; j++)
            #pragma unroll
            for (int q = 0; q < 4; q++) acc[i][j][q] = 0.0f;

    gemm_mainloop(g_xhi, g_xlo, b1h, b1l, g_hhi, g_hlo, b2h, b2l,
                  iters, m0, ncol, smem, acc);

    #pragma unroll
    for (int mf = 0; mf < 2; mf++) {
        #pragma unroll
        for (int nf = 0; nf < 4; nf++) {
            int r0 = m0 + wm * 32 + mf * 16 + g;
            int c  = ncol + wn * 32 + nf * 8 + tig * 2;
            const float* ac = acc[mf][nf];
            size_t p0 = (size_t)r0 * NK + c;
            size_t p1 = p0 + (size_t)8 * NK;
            if (seg == 0) {
                float2 bb = *(const float2*)&bz[c];
                *(float2*)&g_Z[p0] = make_float2(sigf(ac[0] + bb.x), sigf(ac[1] + bb.y));
                *(float2*)&g_Z[p1] = make_float2(sigf(ac[2] + bb.x), sigf(ac[3] + bb.y));
            } else if (seg == 1) {
                float2 bb = *(const float2*)&br[c];
                float2 h0 = *(const float2*)&hprev[p0];
                float2 h1 = *(const float2*)&hprev[p1];
                float v0 = sigf(ac[0] + bb.x) * h0.x;
                float v1 = sigf(ac[1] + bb.y) * h0.y;
                float v2 = sigf(ac[2] + bb.x) * h1.x;
                float v3 = sigf(ac[3] + bb.y) * h1.y;
                uint32_t hi, lo;
                split2(v0, v1, hi, lo);
                *(uint32_t*)&g_rhhi[p0] = hi;
                *(uint32_t*)&g_rhlo[p0] = lo;
                split2(v2, v3, hi, lo);
                *(uint32_t*)&g_rhhi[p1] = hi;
                *(uint32_t*)&g_rhlo[p1] = lo;
            } else {
                *(float2*)&g_WH[p0] = make_float2(ac[0], ac[1]);
                *(float2*)&g_WH[p1] = make_float2(ac[2], ac[3]);
            }
        }
    }
}

// ---------------- stage 2 ----------------
// out = (1 - z) * h + z * tanh( (r*h)@Uh + g_WH + bh )
__global__ __launch_bounds__(NTHR, 1) void gru_s2(
    const float* __restrict__ hprev, const float* __restrict__ bh,
    float* __restrict__ out)
{
    extern __shared__ char smraw[];
    uint32_t smem = smem_u32(smraw);
    const int lane = threadIdx.x & 31;
    const int wid  = threadIdx.x >> 5;
    const int wm = wid >> 2, wn = wid & 3;
    const int g = lane >> 2, tig = lane & 3;

    int ncol = blockIdx.x * BN;
    int m0   = blockIdx.y * BM;
    size_t wsz = (size_t)NK * NK;
    const __nv_bfloat16* bhp = g_whi + (size_t)5 * wsz;
    const __nv_bfloat16* blp = g_wlo + (size_t)5 * wsz;

    float acc[2][4][4];
    #pragma unroll
    for (int i = 0; i < 2; i++)
        #pragma unroll
        for (int j = 0; j < 4; j++)
            #pragma unroll
            for (int q = 0; q < 4; q++) acc[i][j][q] = 0.0f;

    gemm_mainloop(g_rhhi, g_rhlo, bhp, blp, g_rhhi, g_rhlo, bhp, blp,
                  64, m0, ncol, smem, acc);

    #pragma unroll
    for (int mf = 0; mf < 2; mf++) {
        #pragma unroll
        for (int nf = 0; nf < 4; nf++) {
            int r0 = m0 + wm * 32 + mf * 16 + g;
            int c  = ncol + wn * 32 + nf * 8 + tig * 2;
            const float* ac = acc[mf][nf];
            size_t p0 = (size_t)r0 * NK + c;
            size_t p1 = p0 + (size_t)8 * NK;
            float2 bb = *(const float2*)&bh[c];
            float2 w0 = *(const float2*)&g_WH[p0];
            float2 w1 = *(const float2*)&g_WH[p1];
            float2 z0 = *(const float2*)&g_Z[p0];
            float2 z1 = *(const float2*)&g_Z[p1];
            float2 h0 = *(const float2*)&hprev[p0];
            float2 h1 = *(const float2*)&hprev[p1];
            float t0 = tanhf(ac[0] + w0.x + bb.x);
            float t1 = tanhf(ac[1] + w0.y + bb.y);
            float t2 = tanhf(ac[2] + w1.x + bb.x);
            float t3 = tanhf(ac[3] + w1.y + bb.y);
            *(float2*)&out[p0] = make_float2((1.0f - z0.x) * h0.x + z0.x * t0,
                                             (1.0f - z0.y) * h0.y + z0.y * t1);
            *(float2*)&out[p1] = make_float2((1.0f - z1.x) * h1.x + z1.x * t2,
                                             (1.0f - z1.y) * h1.y + z1.y * t3);
        }
    }
}

// ---------------- launch ----------------
extern "C" void kernel_launch(void* const* d_in, const int* in_sizes, int n_in,
                              void* d_out, int out_size)
{
    const float* x  = (const float*)d_in[0];
    const float* h  = (const float*)d_in[1];
    const float* Wz = (const float*)d_in[2];
    const float* Wr = (const float*)d_in[3];
    const float* Wh = (const float*)d_in[4];
    const float* Uz = (const float*)d_in[5];
    const float* Ur = (const float*)d_in[6];
    const float* Uh = (const float*)d_in[7];
    const float* bz = (const float*)d_in[8];
    const float* br = (const float*)d_in[9];
    const float* bh = (const float*)d_in[10];
    float* out = (float*)d_out;

    cudaFuncSetAttribute(gru_s1, cudaFuncAttributeMaxDynamicSharedMemorySize, SMEM_BYTES);
    cudaFuncSetAttribute(gru_s2, cudaFuncAttributeMaxDynamicSharedMemorySize, SMEM_BYTES);

    int n4blocks = (BSZ * NK / 4) / 256;                 // 16384
    cvt_split<<<n4blocks, 256>>>((const float4*)x, 0);
    cvt_split<<<n4blocks, 256>>>((const float4*)h, 1);
    wt_split<<<dim3(64, 64, 6), 256>>>(Wz, Wr, Wh, Uz, Ur, Uh);

    gru_s1<<<dim3(48, 64), NTHR, SMEM_BYTES>>>(h, bz, br);
    gru_s2<<<dim3(16, 64), NTHR, SMEM_BYTES>>>(h, bh, out);
}

// round 9
// speedup vs baseline: 1.1757x; 1.1757x over previous
#include <cuda_runtime.h>
#include <cuda_bf16.h>
#include <cstdint>
#include <math.h>

#define BSZ 8192
#define NK  2048
#define BM  128
#define BN  128
#define BKF 32                    // fp32 K consumed per mainloop iteration
#define TILE_B 8192               // 128 rows x 32 bf16 = 8KB
#define STAGE_B (4*TILE_B)        // Ahi, Alo, Bhi, Blo = 32KB
#define NSTAGE 3
#define SMEM_BYTES (NSTAGE*STAGE_B)   // 96KB -> 2 CTAs/SM

// ---------------- scratch (static device globals; no runtime alloc) ----------------
__device__ __nv_bfloat16 g_xhi[(size_t)BSZ*NK], g_xlo[(size_t)BSZ*NK];
__device__ __nv_bfloat16 g_hhi[(size_t)BSZ*NK], g_hlo[(size_t)BSZ*NK];
__device__ __nv_bfloat16 g_whi[(size_t)6*NK*NK], g_wlo[(size_t)6*NK*NK]; // [w][N][K]
__device__ __nv_bfloat16 g_rhhi[(size_t)BSZ*NK], g_rhlo[(size_t)BSZ*NK];
__device__ float g_Z [(size_t)BSZ*NK];

// ---------------- helpers ----------------
__device__ __forceinline__ uint32_t smem_u32(const void* p) {
    uint32_t a;
    asm("{ .reg .u64 t; cvta.to.shared.u64 t, %1; cvt.u32.u64 %0, t; }" : "=r"(a) : "l"(p));
    return a;
}
__device__ __forceinline__ void cp16(uint32_t dst, const char* src) {
    asm volatile("cp.async.cg.shared.global [%0], [%1], 16;"
                 :: "r"(dst), "l"(src) : "memory");
}
#define CP_COMMIT() asm volatile("cp.async.commit_group;" ::: "memory")
#define CP_WAIT(n)  asm volatile("cp.async.wait_group %0;" :: "n"(n) : "memory")

__device__ __forceinline__ void ldm4(uint32_t* r, uint32_t addr) {
    asm volatile("ldmatrix.sync.aligned.m8n8.x4.shared.b16 {%0,%1,%2,%3}, [%4];"
                 : "=r"(r[0]), "=r"(r[1]), "=r"(r[2]), "=r"(r[3]) : "r"(addr));
}
__device__ __forceinline__ void mma16816(float* d, const uint32_t* a,
                                         uint32_t b0, uint32_t b1) {
    asm volatile(
        "mma.sync.aligned.m16n8k16.row.col.f32.bf16.bf16.f32 "
        "{%0,%1,%2,%3}, {%4,%5,%6,%7}, {%8,%9}, {%0,%1,%2,%3};"
        : "+f"(d[0]), "+f"(d[1]), "+f"(d[2]), "+f"(d[3])
        : "r"(a[0]), "r"(a[1]), "r"(a[2]), "r"(a[3]), "r"(b0), "r"(b1));
}
__device__ __forceinline__ float sigf(float x) { return 1.0f / (1.0f + __expf(-x)); }

__device__ __forceinline__ void split2(float f0, float f1, uint32_t& hi, uint32_t& lo) {
    __nv_bfloat16 h0 = __float2bfloat16_rn(f0);
    __nv_bfloat16 h1 = __float2bfloat16_rn(f1);
    __nv_bfloat16 l0 = __float2bfloat16_rn(f0 - __bfloat162float(h0));
    __nv_bfloat16 l1 = __float2bfloat16_rn(f1 - __bfloat162float(h1));
    hi = (uint32_t)__bfloat16_as_ushort(h0) | ((uint32_t)__bfloat16_as_ushort(h1) << 16);
    lo = (uint32_t)__bfloat16_as_ushort(l0) | ((uint32_t)__bfloat16_as_ushort(l1) << 16);
}

// Swizzled address inside a 128x32-bf16 tile (two logical 64B rows packed per
// 128B line).  row: 0..127, c2: 16B-chunk index within row (0..3).
__device__ __forceinline__ uint32_t swofs(uint32_t row, uint32_t c2) {
    uint32_t p = row >> 1, h = row & 1;
    return p * 128 + (((((h << 2) | c2) ^ (p & 7)) << 4));
}

// ---------------- prep: elementwise split of x and h (one kernel) ----------------
__global__ void cvt_split(const float4* __restrict__ xin, const float4* __restrict__ hin) {
    size_t i = (size_t)blockIdx.x * 256 + threadIdx.x;   // BSZ*NK/4 threads per plane
    int which = blockIdx.y;
    const float4* in = which ? hin : xin;
    uint2* hi = (uint2*)(which ? g_hhi : g_xhi);
    uint2* lo = (uint2*)(which ? g_hlo : g_xlo);
    float4 v = in[i];
    uint32_t h01, l01, h23, l23;
    split2(v.x, v.y, h01, l01);
    split2(v.z, v.w, h23, l23);
    hi[i] = make_uint2(h01, h23);
    lo[i] = make_uint2(l01, l23);
}

// ---------------- prep: transpose + split of all 6 weights ----------------
__global__ void wt_split(const float* __restrict__ W0, const float* __restrict__ W1,
                         const float* __restrict__ W2, const float* __restrict__ W3,
                         const float* __restrict__ W4, const float* __restrict__ W5) {
    __shared__ float t[32][33];
    int w = blockIdx.z;
    const float* src = (w == 0) ? W0 : (w == 1) ? W1 : (w == 2) ? W2
                     : (w == 3) ? W3 : (w == 4) ? W4 : W5;
    int nt = blockIdx.x * 32, kt = blockIdx.y * 32;
    int tx = threadIdx.x & 31, ty = threadIdx.x >> 5;
    #pragma unroll
    for (int j = 0; j < 4; j++) {
        int r = ty + j * 8;
        t[r][tx] = src[(size_t)(kt + r) * NK + nt + tx];
    }
    __syncthreads();
    size_t wbase = (size_t)w * NK * NK;
    #pragma unroll
    for (int j = 0; j < 4; j++) {
        int r = ty + j * 8;
        float v = t[tx][r];
        __nv_bfloat16 hv = __float2bfloat16_rn(v);
        __nv_bfloat16 lv = __float2bfloat16_rn(v - __bfloat162float(hv));
        size_t o = wbase + (size_t)(nt + r) * NK + kt + tx;
        g_whi[o] = hv;
        g_wlo[o] = lv;
    }
}

// ---------------- mma.sync mainloop (shared by both stages) ----------------
// acc += A[m0:m0+128, :] @ B[ncol:ncol+128, :]^T over `iters` chunks of 32
// fp32-K each; switches to operand set 2 at iter 64 (two-pass when iters=128).
__device__ __forceinline__ void gemm_mainloop(
    const __nv_bfloat16* a1h, const __nv_bfloat16* a1l,
    const __nv_bfloat16* b1h, const __nv_bfloat16* b1l,
    const __nv_bfloat16* a2h, const __nv_bfloat16* a2l,
    const __nv_bfloat16* b2h, const __nv_bfloat16* b2l,
    int iters, int m0, int ncol, uint32_t smem,
    float (&acc)[2][8][4])
{
    const int tid  = threadIdx.x;
    const int lane = tid & 31;
    const int wid  = tid >> 5;
    const int wm   = wid >> 1;     // 0..3
    const int wn   = wid & 1;      // 0..1

    // --- cp.async write addressing: 2 chunks per tile per thread ---
    uint32_t swr[2], offMB[2], offNB[2];        // byte offsets
    #pragma unroll
    for (int j = 0; j < 2; j++) {
        int q = tid + j * 256;            // 0..511
        uint32_t row = (uint32_t)q >> 2;  // 0..127
        uint32_t c   = (uint32_t)q & 3;
        swr[j]   = swofs(row, c);
        offMB[j] = ((uint32_t)(m0 + row) * NK + c * 8) * 2;
        offNB[j] = ((uint32_t)(ncol + row) * NK + c * 8) * 2;
    }

    auto loads = [&](int L, uint32_t sb) {
        bool p2 = (L >= 64);
        const char* ah = (const char*)(p2 ? a2h : a1h);
        const char* al = (const char*)(p2 ? a2l : a1l);
        const char* bh = (const char*)(p2 ? b2h : b1h);
        const char* bl = (const char*)(p2 ? b2l : b1l);
        uint32_t kk = ((uint32_t)L & 63u) * (BKF * 2);     // byte offset in K
        #pragma unroll
        for (int j = 0; j < 2; j++) {
            uint32_t om = offMB[j] + kk, on = offNB[j] + kk;
            cp16(sb +            swr[j], ah + om);
            cp16(sb + TILE_B   + swr[j], al + om);
            cp16(sb + 2*TILE_B + swr[j], bh + on);
            cp16(sb + 3*TILE_B + swr[j], bl + on);
        }
        CP_COMMIT();
    };

    // --- ldmatrix read addressing (constants per thread) ---
    const uint32_t r_in = ((lane >> 3) & 1) * 8 + (lane & 7);
    const uint32_t c2b  = (lane >> 4);             // 0 or 1 (16B half of k16)
    uint32_t offA[2][2], offB[4][2];
    #pragma unroll
    for (int mf = 0; mf < 2; mf++)
        #pragma unroll
        for (int ks = 0; ks < 2; ks++)
            offA[mf][ks] = swofs(wm * 32 + mf * 16 + r_in, ks * 2 + c2b);
    #pragma unroll
    for (int nb = 0; nb < 4; nb++)
        #pragma unroll
        for (int ks = 0; ks < 2; ks++)
            offB[nb][ks] = swofs(wn * 64 + nb * 16 + r_in, ks * 2 + c2b);

    auto compute_ks = [&](uint32_t Ah, int ks) {
        uint32_t Al = Ah + TILE_B;
        uint32_t Bh = Ah + 2 * TILE_B;
        uint32_t Bl = Ah + 3 * TILE_B;
        uint32_t a[2][2][4];
        #pragma unroll
        for (int mf = 0; mf < 2; mf++) {
            ldm4(a[mf][0], Ah + offA[mf][ks]);
            ldm4(a[mf][1], Al + offA[mf][ks]);
        }
        #pragma unroll
        for (int nb = 0; nb < 4; nb++) {
            uint32_t bh4[4], bl4[4];
            ldm4(bh4, Bh + offB[nb][ks]);
            ldm4(bl4, Bl + offB[nb][ks]);
            // term-major emission: accumulator reuse distance = 4 MMAs
            #pragma unroll
            for (int mf = 0; mf < 2; mf++)
                #pragma unroll
                for (int hf = 0; hf < 2; hf++)
                    mma16816(acc[mf][nb * 2 + hf], a[mf][0], bh4[hf], bh4[2 + hf]); // hi*hi
            #pragma unroll
            for (int mf = 0; mf < 2; mf++)
                #pragma unroll
                for (int hf = 0; hf < 2; hf++)
                    mma16816(acc[mf][nb * 2 + hf], a[mf][0], bl4[hf], bl4[2 + hf]); // hi*lo
            #pragma unroll
            for (int mf = 0; mf < 2; mf++)
                #pragma unroll
                for (int hf = 0; hf < 2; hf++)
                    mma16816(acc[mf][nb * 2 + hf], a[mf][1], bh4[hf], bh4[2 + hf]); // lo*hi
        }
    };

    const uint32_t send = smem + 3u * STAGE_B;
    loads(0, smem);
    loads(1, smem + STAGE_B);
    uint32_t cs = smem;                 // stage being computed
    uint32_t ls = smem + 2u * STAGE_B;  // stage being loaded (i+2)
    for (int i = 0; i < iters; i++) {
        if (i + 1 < iters) { CP_WAIT(1); } else { CP_WAIT(0); }
        __syncthreads();
        compute_ks(cs, 0);
        if (i + 2 < iters) loads(i + 2, ls);
        compute_ks(cs, 1);
        cs += STAGE_B; if (cs == send) cs = smem;
        ls += STAGE_B; if (ls == send) ls = smem;
    }
}

// ---------------- stage 1 ----------------
// seg 0: g_Z  = sigmoid(x@Wz + h@Uz + bz)
// seg 1: g_rh = split( sigmoid(x@Wr + h@Ur + br) * h )
__global__ __launch_bounds__(256, 2) void gru_s1(
    const float* __restrict__ hprev, const float* __restrict__ bz,
    const float* __restrict__ br)
{
    extern __shared__ char smraw[];
    uint32_t smem = smem_u32(smraw);
    const int lane = threadIdx.x & 31;
    const int wid  = threadIdx.x >> 5;
    const int wm = wid >> 1, wn = wid & 1;
    const int g = lane >> 2, tig = lane & 3;

    int seg  = blockIdx.x >> 4;          // 0 or 1
    int ncol = (blockIdx.x & 15) * BN;
    int m0   = blockIdx.y * BM;
    size_t wsz = (size_t)NK * NK;
    const __nv_bfloat16* b1h = g_whi + (size_t)seg * wsz;          // Wz or Wr
    const __nv_bfloat16* b1l = g_wlo + (size_t)seg * wsz;
    const __nv_bfloat16* b2h = g_whi + (size_t)(3 + seg) * wsz;    // Uz or Ur
    const __nv_bfloat16* b2l = g_wlo + (size_t)(3 + seg) * wsz;

    float acc[2][8][4];
    #pragma unroll
    for (int i = 0; i < 2; i++)
        #pragma unroll
        for (int j = 0; j < 8; j++)
            #pragma unroll
            for (int q = 0; q < 4; q++) acc[i][j][q] = 0.0f;

    gemm_mainloop(g_xhi, g_xlo, b1h, b1l, g_hhi, g_hlo, b2h, b2l,
                  128, m0, ncol, smem, acc);

    #pragma unroll
    for (int mf = 0; mf < 2; mf++) {
        #pragma unroll
        for (int nf = 0; nf < 8; nf++) {
            int r0 = m0 + wm * 32 + mf * 16 + g;
            int c  = ncol + wn * 64 + nf * 8 + tig * 2;
            const float* ac = acc[mf][nf];
            size_t p0 = (size_t)r0 * NK + c;
            size_t p1 = p0 + (size_t)8 * NK;
            if (seg == 0) {
                float2 bb = *(const float2*)&bz[c];
                *(float2*)&g_Z[p0] = make_float2(sigf(ac[0] + bb.x), sigf(ac[1] + bb.y));
                *(float2*)&g_Z[p1] = make_float2(sigf(ac[2] + bb.x), sigf(ac[3] + bb.y));
            } else {
                float2 bb = *(const float2*)&br[c];
                float2 h0 = *(const float2*)&hprev[p0];
                float2 h1 = *(const float2*)&hprev[p1];
                float v0 = sigf(ac[0] + bb.x) * h0.x;
                float v1 = sigf(ac[1] + bb.y) * h0.y;
                float v2 = sigf(ac[2] + bb.x) * h1.x;
                float v3 = sigf(ac[3] + bb.y) * h1.y;
                uint32_t hi, lo;
                split2(v0, v1, hi, lo);
                *(uint32_t*)&g_rhhi[p0] = hi;
                *(uint32_t*)&g_rhlo[p0] = lo;
                split2(v2, v3, hi, lo);
                *(uint32_t*)&g_rhhi[p1] = hi;
                *(uint32_t*)&g_rhlo[p1] = lo;
            }
        }
    }
}

// ---------------- stage 2 ----------------
// acc = x@Wh (pass 1) + (r*h)@Uh (pass 2);
// out = (1 - z) * h + z * tanh(acc + bh)
__global__ __launch_bounds__(256, 2) void gru_s2(
    const float* __restrict__ hprev, const float* __restrict__ bh,
    float* __restrict__ out)
{
    extern __shared__ char smraw[];
    uint32_t smem = smem_u32(smraw);
    const int lane = threadIdx.x & 31;
    const int wid  = threadIdx.x >> 5;
    const int wm = wid >> 1, wn = wid & 1;
    const int g = lane >> 2, tig = lane & 3;

    int ncol = blockIdx.x * BN;
    int m0   = blockIdx.y * BM;
    size_t wsz = (size_t)NK * NK;
    const __nv_bfloat16* whh = g_whi + (size_t)2 * wsz;   // Wh
    const __nv_bfloat16* whl = g_wlo + (size_t)2 * wsz;
    const __nv_bfloat16* uhh = g_whi + (size_t)5 * wsz;   // Uh
    const __nv_bfloat16* uhl = g_wlo + (size_t)5 * wsz;

    float acc[2][8][4];
    #pragma unroll
    for (int i = 0; i < 2; i++)
        #pragma unroll
        for (int j = 0; j < 8; j++)
            #pragma unroll
            for (int q = 0; q < 4; q++) acc[i][j][q] = 0.0f;

    gemm_mainloop(g_xhi, g_xlo, whh, whl, g_rhhi, g_rhlo, uhh, uhl,
                  128, m0, ncol, smem, acc);

    #pragma unroll
    for (int mf = 0; mf < 2; mf++) {
        #pragma unroll
        for (int nf = 0; nf < 8; nf++) {
            int r0 = m0 + wm * 32 + mf * 16 + g;
            int c  = ncol + wn * 64 + nf * 8 + tig * 2;
            const float* ac = acc[mf][nf];
            size_t p0 = (size_t)r0 * NK + c;
            size_t p1 = p0 + (size_t)8 * NK;
            float2 bb = *(const float2*)&bh[c];
            float2 z0 = *(const float2*)&g_Z[p0];
            float2 z1 = *(const float2*)&g_Z[p1];
            float2 h0 = *(const float2*)&hprev[p0];
            float2 h1 = *(const float2*)&hprev[p1];
            float t0 = tanhf(ac[0] + bb.x);
            float t1 = tanhf(ac[1] + bb.y);
            float t2 = tanhf(ac[2] + bb.x);
            float t3 = tanhf(ac[3] + bb.y);
            *(float2*)&out[p0] = make_float2((1.0f - z0.x) * h0.x + z0.x * t0,
                                             (1.0f - z0.y) * h0.y + z0.y * t1);
            *(float2*)&out[p1] = make_float2((1.0f - z1.x) * h1.x + z1.x * t2,
                                             (1.0f - z1.y) * h1.y + z1.y * t3);
        }
    }
}

// ---------------- launch ----------------
extern "C" void kernel_launch(void* const* d_in, const int* in_sizes, int n_in,
                              void* d_out, int out_size)
{
    const float* x  = (const float*)d_in[0];
    const float* h  = (const float*)d_in[1];
    const float* Wz = (const float*)d_in[2];
    const float* Wr = (const float*)d_in[3];
    const float* Wh = (const float*)d_in[4];
    const float* Uz = (const float*)d_in[5];
    const float* Ur = (const float*)d_in[6];
    const float* Uh = (const float*)d_in[7];
    const float* bz = (const float*)d_in[8];
    const float* br = (const float*)d_in[9];
    const float* bh = (const float*)d_in[10];
    float* out = (float*)d_out;

    cudaFuncSetAttribute(gru_s1, cudaFuncAttributeMaxDynamicSharedMemorySize, SMEM_BYTES);
    cudaFuncSetAttribute(gru_s2, cudaFuncAttributeMaxDynamicSharedMemorySize, SMEM_BYTES);

    int n4blocks = (BSZ * NK / 4) / 256;                 // 16384
    cvt_split<<<dim3(n4blocks, 2), 256>>>((const float4*)x, (const float4*)h);
    wt_split<<<dim3(64, 64, 6), 256>>>(Wz, Wr, Wh, Uz, Ur, Uh);

    gru_s1<<<dim3(32, 64), 256, SMEM_BYTES>>>(h, bz, br);
    gru_s2<<<dim3(16, 64), 256, SMEM_BYTES>>>(h, bh, out);
}

// round 10
// speedup vs baseline: 3.2916x; 2.7996x over previous
#include <cuda_runtime.h>
#include <cuda_fp16.h>
#include <cstdint>
#include <math.h>

#define BSZ 8192
#define NK  2048
#define BM  128
#define BN  128
#define BKF 64                     // fp32 K consumed per mainloop iteration
#define TILE_B 16384               // 128 rows x 64 fp16 = 16KB (128B rows)
#define STAGE_B (2*TILE_B)         // A, B = 32KB
#define NSTAGE 3
#define SMEM_BYTES (NSTAGE*STAGE_B)   // 96KB -> 2 CTAs/SM

// ---------------- scratch (static device globals; no runtime alloc) ----------------
__device__ __half g_xh[(size_t)BSZ*NK];
__device__ __half g_hh[(size_t)BSZ*NK];
__device__ __half g_wh[(size_t)6*NK*NK];   // [w][N][K] transposed
__device__ __half g_rh[(size_t)BSZ*NK];
__device__ float  g_Z [(size_t)BSZ*NK];

// ---------------- helpers ----------------
__device__ __forceinline__ uint32_t smem_u32(const void* p) {
    uint32_t a;
    asm("{ .reg .u64 t; cvta.to.shared.u64 t, %1; cvt.u32.u64 %0, t; }" : "=r"(a) : "l"(p));
    return a;
}
__device__ __forceinline__ void cp16(uint32_t dst, const char* src) {
    asm volatile("cp.async.cg.shared.global [%0], [%1], 16;"
                 :: "r"(dst), "l"(src) : "memory");
}
#define CP_COMMIT() asm volatile("cp.async.commit_group;" ::: "memory")
#define CP_WAIT(n)  asm volatile("cp.async.wait_group %0;" :: "n"(n) : "memory")

__device__ __forceinline__ void ldm4(uint32_t* r, uint32_t addr) {
    asm volatile("ldmatrix.sync.aligned.m8n8.x4.shared.b16 {%0,%1,%2,%3}, [%4];"
                 : "=r"(r[0]), "=r"(r[1]), "=r"(r[2]), "=r"(r[3]) : "r"(addr));
}
__device__ __forceinline__ void mma16816(float* d, const uint32_t* a,
                                         uint32_t b0, uint32_t b1) {
    asm volatile(
        "mma.sync.aligned.m16n8k16.row.col.f32.f16.f16.f32 "
        "{%0,%1,%2,%3}, {%4,%5,%6,%7}, {%8,%9}, {%0,%1,%2,%3};"
        : "+f"(d[0]), "+f"(d[1]), "+f"(d[2]), "+f"(d[3])
        : "r"(a[0]), "r"(a[1]), "r"(a[2]), "r"(a[3]), "r"(b0), "r"(b1));
}
__device__ __forceinline__ float sigf(float x) { return 1.0f / (1.0f + __expf(-x)); }

__device__ __forceinline__ uint32_t pack_h2(float a, float b) {
    __half2 h = __floats2half2_rn(a, b);
    return *(uint32_t*)&h;
}

// Swizzled byte address inside a 128x64-fp16 tile (128B per row, SW128).
// row: 0..127, c: 16B-chunk index within row (0..7).
__device__ __forceinline__ uint32_t swz(uint32_t row, uint32_t c) {
    return row * 128 + ((c ^ (row & 7)) << 4);
}

// ---------------- prep: convert x and h to fp16 (one kernel) ----------------
__global__ void cvt_half(const float4* __restrict__ xin, const float4* __restrict__ hin) {
    size_t i = (size_t)blockIdx.x * 256 + threadIdx.x;   // BSZ*NK/4 threads per plane
    int which = blockIdx.y;
    const float4* in = which ? hin : xin;
    uint2* dst = (uint2*)(which ? g_hh : g_xh);
    float4 v = in[i];
    dst[i] = make_uint2(pack_h2(v.x, v.y), pack_h2(v.z, v.w));
}

// ---------------- prep: transpose + convert all 6 weights ----------------
__global__ void wt_cvt(const float* __restrict__ W0, const float* __restrict__ W1,
                       const float* __restrict__ W2, const float* __restrict__ W3,
                       const float* __restrict__ W4, const float* __restrict__ W5) {
    __shared__ float t[32][33];
    int w = blockIdx.z;
    const float* src = (w == 0) ? W0 : (w == 1) ? W1 : (w == 2) ? W2
                     : (w == 3) ? W3 : (w == 4) ? W4 : W5;
    int nt = blockIdx.x * 32, kt = blockIdx.y * 32;
    int tx = threadIdx.x & 31, ty = threadIdx.x >> 5;
    #pragma unroll
    for (int j = 0; j < 4; j++) {
        int r = ty + j * 8;
        t[r][tx] = src[(size_t)(kt + r) * NK + nt + tx];
    }
    __syncthreads();
    size_t wbase = (size_t)w * NK * NK;
    #pragma unroll
    for (int j = 0; j < 4; j++) {
        int r = ty + j * 8;
        g_wh[wbase + (size_t)(nt + r) * NK + kt + tx] = __float2half_rn(t[tx][r]);
    }
}

// ---------------- fp16 mma.sync mainloop (shared by both stages) ----------------
// acc += A[m0:m0+128, :] @ B[ncol:ncol+128, :]^T over `iters` chunks of 64
// fp32-K each; switches to operand set 2 at iter 32 (two-pass when iters=64).
__device__ __forceinline__ void gemm_mainloop(
    const __half* a1, const __half* b1,
    const __half* a2, const __half* b2,
    int iters, int m0, int ncol, uint32_t smem,
    float (&acc)[2][8][4])
{
    const int tid  = threadIdx.x;
    const int lane = tid & 31;
    const int wid  = tid >> 5;
    const int wm   = wid >> 1;     // 0..3
    const int wn   = wid & 1;      // 0..1

    // --- cp.async write addressing: 4 chunks per 16KB tile per thread ---
    // j-step = +32 rows => row&7 unchanged => address step is a constant.
    const uint32_t row0 = (uint32_t)tid >> 3;     // 0..31
    const uint32_t cch  = (uint32_t)tid & 7;
    const uint32_t swr0  = swz(row0, cch);
    const uint32_t offM0 = ((uint32_t)(m0 + row0) * NK + cch * 8) * 2;
    const uint32_t offN0 = ((uint32_t)(ncol + row0) * NK + cch * 8) * 2;

    auto loads = [&](int L, uint32_t sb) {
        bool p2 = (L >= 32);
        const char* ap = (const char*)(p2 ? a2 : a1);
        const char* bp = (const char*)(p2 ? b2 : b1);
        uint32_t kk = ((uint32_t)L & 31u) * (BKF * 2);     // byte offset in K
        #pragma unroll
        for (int j = 0; j < 4; j++) {
            uint32_t sw = swr0 + (uint32_t)j * 32u * 128u;
            uint32_t go = (uint32_t)j * 32u * NK * 2u + kk;
            cp16(sb +          sw, ap + offM0 + go);
            cp16(sb + TILE_B + sw, bp + offN0 + go);
        }
        CP_COMMIT();
    };

    // --- ldmatrix read addressing (base per ks; mf/nb derived by row-step) ---
    const uint32_t r_in = ((lane >> 3) & 1) * 8 + (lane & 7);
    const uint32_t c2b  = (lane >> 4);             // 0 or 1 (16B half of k16)
    uint32_t offA0[4], offB0[4];
    #pragma unroll
    for (int ks = 0; ks < 4; ks++) {
        offA0[ks] = swz(wm * 32 + r_in, ks * 2 + c2b);
        offB0[ks] = swz(wn * 64 + r_in, ks * 2 + c2b);
    }

    auto compute_ks = [&](uint32_t Ah, int ks) {
        uint32_t Bh = Ah + TILE_B;
        uint32_t a[2][4];
        #pragma unroll
        for (int mf = 0; mf < 2; mf++)
            ldm4(a[mf], Ah + offA0[ks] + (uint32_t)mf * 16u * 128u);
        #pragma unroll
        for (int nb = 0; nb < 4; nb++) {
            uint32_t b4[4];
            ldm4(b4, Bh + offB0[ks] + (uint32_t)nb * 16u * 128u);
            #pragma unroll
            for (int mf = 0; mf < 2; mf++)
                #pragma unroll
                for (int hf = 0; hf < 2; hf++)
                    mma16816(acc[mf][nb * 2 + hf], a[mf], b4[hf], b4[2 + hf]);
        }
    };

    const uint32_t send = smem + 3u * STAGE_B;
    loads(0, smem);
    loads(1, smem + STAGE_B);
    uint32_t cs = smem;                 // stage being computed
    uint32_t ls = smem + 2u * STAGE_B;  // stage being loaded (i+2)
    for (int i = 0; i < iters; i++) {
        if (i + 1 < iters) { CP_WAIT(1); } else { CP_WAIT(0); }
        __syncthreads();
        compute_ks(cs, 0);
        compute_ks(cs, 1);
        if (i + 2 < iters) loads(i + 2, ls);
        compute_ks(cs, 2);
        compute_ks(cs, 3);
        cs += STAGE_B; if (cs == send) cs = smem;
        ls += STAGE_B; if (ls == send) ls = smem;
    }
}

// ---------------- stage 1 ----------------
// seg 0: g_Z  = sigmoid(x@Wz + h@Uz + bz)
// seg 1: g_rh = fp16( sigmoid(x@Wr + h@Ur + br) * h )
__global__ __launch_bounds__(256, 2) void gru_s1(
    const float* __restrict__ hprev, const float* __restrict__ bz,
    const float* __restrict__ br)
{
    extern __shared__ char smraw[];
    uint32_t smem = smem_u32(smraw);
    const int lane = threadIdx.x & 31;
    const int wid  = threadIdx.x >> 5;
    const int wm = wid >> 1, wn = wid & 1;
    const int g = lane >> 2, tig = lane & 3;

    int seg  = blockIdx.x >> 4;          // 0 or 1
    int ncol = (blockIdx.x & 15) * BN;
    int m0   = blockIdx.y * BM;
    size_t wsz = (size_t)NK * NK;
    const __half* b1 = g_wh + (size_t)seg * wsz;          // Wz or Wr
    const __half* b2 = g_wh + (size_t)(3 + seg) * wsz;    // Uz or Ur

    float acc[2][8][4];
    #pragma unroll
    for (int i = 0; i < 2; i++)
        #pragma unroll
        for (int j = 0; j < 8; j++)
            #pragma unroll
            for (int q = 0; q < 4; q++) acc[i][j][q] = 0.0f;

    gemm_mainloop(g_xh, b1, g_hh, b2, 64, m0, ncol, smem, acc);

    #pragma unroll
    for (int mf = 0; mf < 2; mf++) {
        #pragma unroll
        for (int nf = 0; nf < 8; nf++) {
            int r0 = m0 + wm * 32 + mf * 16 + g;
            int c  = ncol + wn * 64 + nf * 8 + tig * 2;
            const float* ac = acc[mf][nf];
            size_t p0 = (size_t)r0 * NK + c;
            size_t p1 = p0 + (size_t)8 * NK;
            if (seg == 0) {
                float2 bb = *(const float2*)&bz[c];
                *(float2*)&g_Z[p0] = make_float2(sigf(ac[0] + bb.x), sigf(ac[1] + bb.y));
                *(float2*)&g_Z[p1] = make_float2(sigf(ac[2] + bb.x), sigf(ac[3] + bb.y));
            } else {
                float2 bb = *(const float2*)&br[c];
                float2 h0 = *(const float2*)&hprev[p0];
                float2 h1 = *(const float2*)&hprev[p1];
                *(uint32_t*)&g_rh[p0] = pack_h2(sigf(ac[0] + bb.x) * h0.x,
                                                sigf(ac[1] + bb.y) * h0.y);
                *(uint32_t*)&g_rh[p1] = pack_h2(sigf(ac[2] + bb.x) * h1.x,
                                                sigf(ac[3] + bb.y) * h1.y);
            }
        }
    }
}

// ---------------- stage 2 ----------------
// acc = x@Wh (pass 1) + (r*h)@Uh (pass 2);
// out = (1 - z) * h + z * tanh(acc + bh)
__global__ __launch_bounds__(256, 2) void gru_s2(
    const float* __restrict__ hprev, const float* __restrict__ bh,
    float* __restrict__ out)
{
    extern __shared__ char smraw[];
    uint32_t smem = smem_u32(smraw);
    const int lane = threadIdx.x & 31;
    const int wid  = threadIdx.x >> 5;
    const int wm = wid >> 1, wn = wid & 1;
    const int g = lane >> 2, tig = lane & 3;

    int ncol = blockIdx.x * BN;
    int m0   = blockIdx.y * BM;
    size_t wsz = (size_t)NK * NK;
    const __half* wh = g_wh + (size_t)2 * wsz;   // Wh
    const __half* uh = g_wh + (size_t)5 * wsz;   // Uh

    float acc[2][8][4];
    #pragma unroll
    for (int i = 0; i < 2; i++)
        #pragma unroll
        for (int j = 0; j < 8; j++)
            #pragma unroll
            for (int q = 0; q < 4; q++) acc[i][j][q] = 0.0f;

    gemm_mainloop(g_xh, wh, g_rh, uh, 64, m0, ncol, smem, acc);

    #pragma unroll
    for (int mf = 0; mf < 2; mf++) {
        #pragma unroll
        for (int nf = 0; nf < 8; nf++) {
            int r0 = m0 + wm * 32 + mf * 16 + g;
            int c  = ncol + wn * 64 + nf * 8 + tig * 2;
            const float* ac = acc[mf][nf];
            size_t p0 = (size_t)r0 * NK + c;
            size_t p1 = p0 + (size_t)8 * NK;
            float2 bb = *(const float2*)&bh[c];
            float2 z0 = *(const float2*)&g_Z[p0];
            float2 z1 = *(const float2*)&g_Z[p1];
            float2 h0 = *(const float2*)&hprev[p0];
            float2 h1 = *(const float2*)&hprev[p1];
            float t0 = tanhf(ac[0] + bb.x);
            float t1 = tanhf(ac[1] + bb.y);
            float t2 = tanhf(ac[2] + bb.x);
            float t3 = tanhf(ac[3] + bb.y);
            *(float2*)&out[p0] = make_float2((1.0f - z0.x) * h0.x + z0.x * t0,
                                             (1.0f - z0.y) * h0.y + z0.y * t1);
            *(float2*)&out[p1] = make_float2((1.0f - z1.x) * h1.x + z1.x * t2,
                                             (1.0f - z1.y) * h1.y + z1.y * t3);
        }
    }
}

// ---------------- launch ----------------
extern "C" void kernel_launch(void* const* d_in, const int* in_sizes, int n_in,
                              void* d_out, int out_size)
{
    const float* x  = (const float*)d_in[0];
    const float* h  = (const float*)d_in[1];
    const float* Wz = (const float*)d_in[2];
    const float* Wr = (const float*)d_in[3];
    const float* Wh = (const float*)d_in[4];
    const float* Uz = (const float*)d_in[5];
    const float* Ur = (const float*)d_in[6];
    const float* Uh = (const float*)d_in[7];
    const float* bz = (const float*)d_in[8];
    const float* br = (const float*)d_in[9];
    const float* bh = (const float*)d_in[10];
    float* out = (float*)d_out;

    cudaFuncSetAttribute(gru_s1, cudaFuncAttributeMaxDynamicSharedMemorySize, SMEM_BYTES);
    cudaFuncSetAttribute(gru_s2, cudaFuncAttributeMaxDynamicSharedMemorySize, SMEM_BYTES);

    int n4blocks = (BSZ * NK / 4) / 256;                 // 16384
    cvt_half<<<dim3(n4blocks, 2), 256>>>((const float4*)x, (const float4*)h);
    wt_cvt<<<dim3(64, 64, 6), 256>>>(Wz, Wr, Wh, Uz, Ur, Uh);

    gru_s1<<<dim3(32, 64), 256, SMEM_BYTES>>>(h, bz, br);
    gru_s2<<<dim3(16, 64), 256, SMEM_BYTES>>>(h, bh, out);
}